// round 15
// baseline (speedup 1.0000x reference)
#include <cuda_runtime.h>
#include <math.h>
#include <stdint.h>

#define HIDDEN 4096
#define NEXP   128
#define TOPK   8
#define TM     64                     // tokens per CTA (halved: reg headroom)
#define KCH    32

#define KT_CHUNKS 59                  // tensor path: k in [0, 1888)
#define KF_CHUNKS 69                  // fma path:    k in [1888, 4096)
#define K_T       1888

// tensor-path smem: PITCH-36 fp32 k8 regions (proven layout)
#define PITCH   36
#define K8SA    (64 * PITCH + 32)     // 2336  (A: 64 rows)
#define K8SB    (128 * PITCH + 32)    // 4640  (B: 128 experts)
#define TEN_BOFF (4 * K8SA)           // 9344
#define TEN_STAGE (TEN_BOFF + 4 * K8SB) // 27904
#define TEN0    0
#define TEN1    TEN_STAGE

// fma-path smem: A duplicated 8B/token (64 tok), B 12-float blocks (R6 layout)
#define FA_ROW  512                   // bytes per k-row of dup A (64 tok * 8B)
#define FB_ROW  768                   // bytes per k-row of B (16 blocks * 48B)
#define FS_A    (KCH * FA_ROW)        // 16384
#define FS_B    (KCH * FB_ROW)        // 24576
#define FMA_STAGE (FS_A + FS_B)       // 40960
#define FMA0    (2 * TEN_STAGE)       // 55808
#define FMA1    (FMA0 + FMA_STAGE)    // 96768

#define SMEM_BYTES (FMA1 + FMA_STAGE) // 137728
#define LPITCH  132

#define DELTA   1.5e-4f
#define RB      8

__device__ int g_ctr;
__device__ int g_list[16384];

#define BAR(id) asm volatile("bar.sync %0, %1;" :: "r"(id), "r"(256) : "memory")

__device__ __forceinline__ void split_bf16(float x, float y, uint32_t& h, uint32_t& l) {
    asm("cvt.rn.bf16x2.f32 %0, %1, %2;" : "=r"(h) : "f"(y), "f"(x));
    float h0 = __uint_as_float(h << 16);
    float h1 = __uint_as_float(h & 0xffff0000u);
    asm("cvt.rn.bf16x2.f32 %0, %1, %2;" : "=r"(l) : "f"(y - h1), "f"(x - h0));
}

__device__ __forceinline__ void mma16(float d[4], const uint32_t a[4], const uint32_t b[2]) {
    asm volatile(
        "mma.sync.aligned.m16n8k16.row.col.f32.bf16.bf16.f32 "
        "{%0,%1,%2,%3}, {%4,%5,%6,%7}, {%8,%9}, {%0,%1,%2,%3};\n"
        : "+f"(d[0]), "+f"(d[1]), "+f"(d[2]), "+f"(d[3])
        : "r"(a[0]), "r"(a[1]), "r"(a[2]), "r"(a[3]),
          "r"(b[0]), "r"(b[1]));
}

__device__ __forceinline__ void ffma2(unsigned long long& d,
                                      unsigned long long a,
                                      unsigned long long b) {
    asm("fma.rn.f32x2 %0, %1, %2, %0;" : "+l"(d) : "l"(a), "l"(b));
}

__global__ void zero_ctr_kernel() { g_ctr = 0; }

// ---------------------------------------------------------------------------
// Hybrid dual-pipe router, TM=64, 512 threads. Warps 0-7: bf16x3 mma over
// k[0,1888) (warp tile 64x16, acc=32 regs). Warps 8-15: FFMA2 fp32 over
// k[1888,4096) (4tok x 8exp, acc=32 regs). Partial logits in disjoint smem;
// top-9 + near-tie detection; exact fp32 refine.
// ---------------------------------------------------------------------------
__global__ void __launch_bounds__(512, 1) router_fused(
    const float* __restrict__ X, const float* __restrict__ W,
    const float* __restrict__ bias, float* __restrict__ out, int T)
{
    extern __shared__ char smem[];
    const int tid  = threadIdx.x;
    const int wid  = tid >> 5;
    const int lane = tid & 31;
    const int m0   = blockIdx.x * TM;

    float* L  = (float*)smem;            // tensor partial [64][LPITCH]
    float* L2 = (float*)(smem + FMA0);   // fma partial    [64][LPITCH]

    if (wid < 8) {
        // ============== TENSOR PATH (warps 0-7, tid 0..255) ================
        const int wn = wid;                  // experts [wn*16, wn*16+16)
        const int g  = lane >> 2;
        const int t  = lane & 3;
        const int c4  = tid & 7;
        const int k8p = c4 >> 1;
        const int kkb = (c4 & 1) * 4;
        const int pr0 = tid >> 3;            // 0..31

        float acc[4][2][4];
#pragma unroll
        for (int i = 0; i < 4; i++)
#pragma unroll
            for (int j = 0; j < 2; j++)
#pragma unroll
                for (int q = 0; q < 4; q++) acc[i][j][q] = 0.f;

        // prologue: produce chunk 0 into TEN0
#pragma unroll
        for (int i = 0; i < 2; i++) {        // A: 64 rows
            const int row = pr0 + 32 * i;
            float4 va = *(const float4*)(X + (size_t)(m0 + row) * HIDDEN + c4 * 4);
            float* pA = (float*)(smem + TEN0 + k8p * K8SA + row * PITCH + kkb * 4);
            pA[0] = va.x; pA[1] = va.y; pA[2] = va.z; pA[3] = va.w;
        }
#pragma unroll
        for (int i = 0; i < 4; i++) {        // B: 128 experts
            const int row = pr0 + 32 * i;
            float4 vb = *(const float4*)(W + (size_t)row * HIDDEN + c4 * 4);
            float* pB = (float*)(smem + TEN0 + TEN_BOFF + k8p * K8SB + row * PITCH + kkb * 4);
            pB[0] = vb.x; pB[1] = vb.y; pB[2] = vb.z; pB[3] = vb.w;
        }

        for (int c = 0; c < KT_CHUNKS; c++) {
            BAR(1);
            const char* sp = smem + ((c & 1) ? TEN1 : TEN0);
            char* sn = (char*)smem + (((c + 1) & 1) ? TEN1 : TEN0);
            const bool pf = (c + 1 < KT_CHUNKS);
            const int k0 = (c + 1) * KCH;

            float4 xa[2], wa[4];
            if (pf) {
#pragma unroll
                for (int i = 0; i < 2; i++) {
                    const int row = pr0 + 32 * i;
                    xa[i] = *(const float4*)(X + (size_t)(m0 + row) * HIDDEN + k0 + c4 * 4);
                }
#pragma unroll
                for (int i = 0; i < 4; i++) {
                    const int row = pr0 + 32 * i;
                    wa[i] = *(const float4*)(W + (size_t)row * HIDDEN + k0 + c4 * 4);
                }
            }

#pragma unroll
            for (int h = 0; h < 2; h++) {
                const char* a0p = sp + (2 * h + 0) * K8SA;
                const char* a1p = sp + (2 * h + 1) * K8SA;
                const char* b0p = sp + TEN_BOFF + (2 * h + 0) * K8SB;
                const char* b1p = sp + TEN_BOFF + (2 * h + 1) * K8SB;

                uint32_t bh[2][2], bl[2][2];
#pragma unroll
                for (int jj = 0; jj < 2; jj++) {
                    const int e = wn * 16 + jj * 8 + g;
                    const char* r0 = b0p + e * PITCH + t * 8;
                    const char* r1 = b1p + e * PITCH + t * 8;
                    split_bf16(*(const float*)(r0), *(const float*)(r0 + 4),
                               bh[jj][0], bl[jj][0]);
                    split_bf16(*(const float*)(r1), *(const float*)(r1 + 4),
                               bh[jj][1], bl[jj][1]);
                }
#pragma unroll
                for (int i = 0; i < 4; i++) {
                    const int ra = i * 16 + g;
                    const char* q0 = a0p + ra * PITCH + t * 8;
                    const char* q1 = a0p + (ra + 8) * PITCH + t * 8;
                    const char* q2 = a1p + ra * PITCH + t * 8;
                    const char* q3 = a1p + (ra + 8) * PITCH + t * 8;
                    uint32_t ah[4], al[4];
                    split_bf16(*(const float*)(q0), *(const float*)(q0 + 4), ah[0], al[0]);
                    split_bf16(*(const float*)(q1), *(const float*)(q1 + 4), ah[1], al[1]);
                    split_bf16(*(const float*)(q2), *(const float*)(q2 + 4), ah[2], al[2]);
                    split_bf16(*(const float*)(q3), *(const float*)(q3 + 4), ah[3], al[3]);
#pragma unroll
                    for (int jj = 0; jj < 2; jj++) {
                        mma16(acc[i][jj], ah, bh[jj]);
                        mma16(acc[i][jj], al, bh[jj]);
                        mma16(acc[i][jj], ah, bl[jj]);
                    }
                }
            }

            if (pf) {
#pragma unroll
                for (int i = 0; i < 2; i++) {
                    const int row = pr0 + 32 * i;
                    float* pA = (float*)(sn + k8p * K8SA + row * PITCH + kkb * 4);
                    pA[0] = xa[i].x; pA[1] = xa[i].y; pA[2] = xa[i].z; pA[3] = xa[i].w;
                }
#pragma unroll
                for (int i = 0; i < 4; i++) {
                    const int row = pr0 + 32 * i;
                    float* pB = (float*)(sn + TEN_BOFF + k8p * K8SB + row * PITCH + kkb * 4);
                    pB[0] = wa[i].x; pB[1] = wa[i].y; pB[2] = wa[i].z; pB[3] = wa[i].w;
                }
            }
        }

        BAR(1);   // tensor warps done reading stages -> overwrite with L
#pragma unroll
        for (int i = 0; i < 4; i++) {
            const int r0 = i * 16 + g;
#pragma unroll
            for (int jj = 0; jj < 2; jj++) {
                const int c0 = wn * 16 + jj * 8 + t * 2;
                *(float2*)&L[r0 * LPITCH + c0]       = make_float2(acc[i][jj][0], acc[i][jj][1]);
                *(float2*)&L[(r0 + 8) * LPITCH + c0] = make_float2(acc[i][jj][2], acc[i][jj][3]);
            }
        }
    } else {
        // ============== FMA PATH (warps 8-15, tidf 0..255) =================
        const int tidf = tid - 256;
        const int tx = tidf & 15;            // expert block (8 experts)
        const int ty = tidf >> 4;            // token block (4 tokens), 0..15
        // producer maps:
        //  A: lane-major token (32 distinct toks per warp -> conflict-free STS.64)
        const int ptok  = (tidf & 31) | ((tidf >> 7) << 5);   // 0..63
        const int psbase = ((tidf >> 5) & 3) * 2;             // slots {psbase, psbase+1}
        //  B: R6-proven block layout
        const int lr = tidf >> 1;            // expert 0..127
        const int lc = (tidf & 1) * 4;
        const int wslot = ((lr >> 3) * 12 + (lr & 7)) * 4;

        unsigned long long acc2[4][4];
#pragma unroll
        for (int i = 0; i < 4; i++)
#pragma unroll
            for (int j = 0; j < 4; j++) acc2[i][j] = 0ull;

        // prologue: produce chunk 0 into FMA0
#pragma unroll
        for (int gidx = 0; gidx < 2; gidx++) {
            const int s = psbase + gidx;                     // k slot 0..7 (4 k each)
            float4 xv = *(const float4*)(X + (size_t)(m0 + ptok) * HIDDEN + K_T + s * 4);
            const float xf[4] = {xv.x, xv.y, xv.z, xv.w};
#pragma unroll
            for (int j = 0; j < 4; j++)
                *(float2*)(smem + FMA0 + (s * 4 + j) * FA_ROW + ptok * 8) = make_float2(xf[j], xf[j]);
        }
#pragma unroll
        for (int s = 0; s < 4; s++) {
            float4 wv = *(const float4*)(W + (size_t)lr * HIDDEN + K_T + s * 8 + lc);
            const float wf[4] = {wv.x, wv.y, wv.z, wv.w};
#pragma unroll
            for (int j = 0; j < 4; j++)
                *(float*)(smem + FMA0 + FS_A + (s * 8 + lc + j) * FB_ROW + wslot) = wf[j];
        }

        for (int c = 0; c < KF_CHUNKS; c++) {
            BAR(2);
            const char* sp = smem + ((c & 1) ? FMA1 : FMA0);
            char* sn = (char*)smem + (((c + 1) & 1) ? FMA1 : FMA0);
            const bool pf = (c + 1 < KF_CHUNKS);
            const int k0 = K_T + (c + 1) * KCH;

            float4 xpre[2], wpre[4];
            if (pf) {
#pragma unroll
                for (int gidx = 0; gidx < 2; gidx++) {
                    const int s = psbase + gidx;
                    xpre[gidx] = *(const float4*)(X + (size_t)(m0 + ptok) * HIDDEN + k0 + s * 4);
                }
#pragma unroll
                for (int s = 0; s < 4; s++)
                    wpre[s] = *(const float4*)(W + (size_t)lr * HIDDEN + k0 + s * 8 + lc);
            }

#pragma unroll 4
            for (int kk = 0; kk < KCH; kk++) {
                const char* ab = sp + kk * FA_ROW + ty * 32;
                ulonglong2 a01 = *(const ulonglong2*)(ab);
                ulonglong2 a23 = *(const ulonglong2*)(ab + 16);
                const char* bb = sp + FS_A + kk * FB_ROW + tx * 48;
                ulonglong2 b01 = *(const ulonglong2*)(bb);
                ulonglong2 b23 = *(const ulonglong2*)(bb + 16);
                unsigned long long ar[4] = {a01.x, a01.y, a23.x, a23.y};
                unsigned long long br[4] = {b01.x, b01.y, b23.x, b23.y};
#pragma unroll
                for (int i = 0; i < 4; i++)
#pragma unroll
                    for (int j = 0; j < 4; j++)
                        ffma2(acc2[i][j], ar[i], br[j]);
            }

            if (pf) {
#pragma unroll
                for (int gidx = 0; gidx < 2; gidx++) {
                    const int s = psbase + gidx;
                    const float xf[4] = {xpre[gidx].x, xpre[gidx].y, xpre[gidx].z, xpre[gidx].w};
#pragma unroll
                    for (int j = 0; j < 4; j++)
                        *(float2*)(sn + (s * 4 + j) * FA_ROW + ptok * 8) = make_float2(xf[j], xf[j]);
                }
#pragma unroll
                for (int s = 0; s < 4; s++) {
                    const float wf[4] = {wpre[s].x, wpre[s].y, wpre[s].z, wpre[s].w};
#pragma unroll
                    for (int j = 0; j < 4; j++)
                        *(float*)(sn + FS_A + (s * 8 + lc + j) * FB_ROW + wslot) = wf[j];
                }
            }
        }

        BAR(2);   // fma warps done reading stages -> overwrite with L2
#pragma unroll
        for (int i = 0; i < 4; i++) {
            const int tok = ty * 4 + i;
#pragma unroll
            for (int j = 0; j < 4; j++) {
                float2 v = *(float2*)&acc2[i][j];
                *(float2*)&L2[tok * LPITCH + tx * 8 + j * 2] = v;
            }
        }
    }

    __syncthreads();

    // ---- top-9 (scores = L + L2) with risk detection; 16 warps x 4 rows ----
    float bv[4];
#pragma unroll
    for (int q = 0; q < 4; q++) bv[q] = bias[q * 32 + lane];

    for (int rr = 0; rr < 4; rr++) {
        const int row = wid * 4 + rr;
        const float* Lr  = L  + row * LPITCH;
        const float* Lr2 = L2 + row * LPITCH;

        float sv[4], wv[4];
#pragma unroll
        for (int q = 0; q < 4; q++) {
            float logit = Lr[q * 32 + lane] + Lr2[q * 32 + lane];
            float sc = 1.f / (1.f + expf(-logit));
            wv[q] = sc;
            sv[q] = sc + bv[q];
        }

        float wsel[TOPK];
        int   isel[TOPK];
        float wsum = 0.f;
        float prev = 0.f, mingap = INFINITY;

#pragma unroll
        for (int k = 0; k < TOPK + 1; k++) {
            float bs = -INFINITY; int bi = 0x7fffffff; float bw = 0.f;
#pragma unroll
            for (int q = 0; q < 4; q++) {
                int e = q * 32 + lane;
                if (sv[q] > bs || (sv[q] == bs && e < bi)) { bs = sv[q]; bi = e; bw = wv[q]; }
            }
#pragma unroll
            for (int off = 16; off; off >>= 1) {
                float os = __shfl_xor_sync(0xffffffffu, bs, off);
                int   oi = __shfl_xor_sync(0xffffffffu, bi, off);
                float ow = __shfl_xor_sync(0xffffffffu, bw, off);
                if (os > bs || (os == bs && oi < bi)) { bs = os; bi = oi; bw = ow; }
            }
            if (k > 0) mingap = fminf(mingap, prev - bs);
            prev = bs;
            if (k < TOPK) {
                isel[k] = bi; wsel[k] = bw; wsum += bw;
#pragma unroll
                for (int q = 0; q < 4; q++)
                    if (q * 32 + lane == bi) sv[q] = -INFINITY;
            }
        }

        if (lane == 0) {
            const int token = m0 + row;
            float inv = 1.f / (wsum + 1e-20f);   // ROUTED_SCALING = 1.0
#pragma unroll
            for (int k = 0; k < TOPK; k++) {
                out[(size_t)token * TOPK + k]                    = (float)isel[k];
                out[(size_t)T * TOPK + (size_t)token * TOPK + k] = wsel[k] * inv;
            }
            if (!(mingap >= DELTA)) {
                int idx = atomicAdd(&g_ctr, 1);
                g_list[idx] = token;
            }
        }
    }
}

// ---------------------------------------------------------------------------
// Exact fp32 refine of risky tokens (proven, unchanged).
// ---------------------------------------------------------------------------
__global__ void __launch_bounds__(256) refine_kernel(
    const float* __restrict__ X, const float* __restrict__ W,
    const float* __restrict__ bias, float* __restrict__ out, int T)
{
    __shared__ float Xs[RB][512];
    __shared__ float S[RB][NEXP];
    __shared__ int   tks[RB];

    const int tid  = threadIdx.x;
    const int e    = tid & 127;
    const int tg   = tid >> 7;
    const int wid  = tid >> 5;
    const int lane = tid & 31;
    const int R    = g_ctr;

    for (int b = blockIdx.x; b * RB < R; b += gridDim.x) {
        if (tid < RB) {
            int i = b * RB + tid;
            tks[tid] = (i < R) ? g_list[i] : -1;
        }
        __syncthreads();

        float acc[4] = {0.f, 0.f, 0.f, 0.f};
        const float* wrow = W + (size_t)e * HIDDEN;

        for (int c = 0; c < 8; c++) {
            const int k0 = c * 512;
#pragma unroll
            for (int i = 0; i < 4; i++) {
                int s   = tid + 256 * i;
                int tok = s >> 7;
                int f4  = s & 127;
                int tt  = tks[tok] < 0 ? 0 : tks[tok];
                *(float4*)&Xs[tok][f4 * 4] =
                    *(const float4*)(X + (size_t)tt * HIDDEN + k0 + f4 * 4);
            }
            __syncthreads();
#pragma unroll 4
            for (int f4 = 0; f4 < 128; f4++) {
                float4 w4 = *(const float4*)(wrow + k0 + f4 * 4);
#pragma unroll
                for (int j = 0; j < 4; j++) {
                    const float* xr = &Xs[tg * 4 + j][f4 * 4];
                    acc[j] = fmaf(w4.x, xr[0],
                             fmaf(w4.y, xr[1],
                             fmaf(w4.z, xr[2],
                             fmaf(w4.w, xr[3], acc[j]))));
                }
            }
            __syncthreads();
        }
#pragma unroll
        for (int j = 0; j < 4; j++) S[tg * 4 + j][e] = acc[j];
        __syncthreads();

        if (wid < RB && tks[wid] >= 0) {
            const int token = tks[wid];
            float sv[4], wv[4];
#pragma unroll
            for (int q = 0; q < 4; q++) {
                int ee = q * 32 + lane;
                float sc = 1.f / (1.f + expf(-S[wid][ee]));
                wv[q] = sc;
                sv[q] = sc + bias[ee];
            }
            float wsel[TOPK]; int isel[TOPK]; float wsum = 0.f;
#pragma unroll
            for (int k = 0; k < TOPK; k++) {
                float bs = -INFINITY; int bi = 0x7fffffff; float bw = 0.f;
#pragma unroll
                for (int q = 0; q < 4; q++) {
                    int ee = q * 32 + lane;
                    if (sv[q] > bs || (sv[q] == bs && ee < bi)) { bs = sv[q]; bi = ee; bw = wv[q]; }
                }
#pragma unroll
                for (int off = 16; off; off >>= 1) {
                    float os = __shfl_xor_sync(0xffffffffu, bs, off);
                    int   oi = __shfl_xor_sync(0xffffffffu, bi, off);
                    float ow = __shfl_xor_sync(0xffffffffu, bw, off);
                    if (os > bs || (os == bs && oi < bi)) { bs = os; bi = oi; bw = ow; }
                }
                isel[k] = bi; wsel[k] = bw; wsum += bw;
#pragma unroll
                for (int q = 0; q < 4; q++)
                    if (q * 32 + lane == bi) sv[q] = -INFINITY;
            }
            if (lane == 0) {
                float inv = 1.f / (wsum + 1e-20f);
#pragma unroll
                for (int k = 0; k < TOPK; k++) {
                    out[(size_t)token * TOPK + k]                    = (float)isel[k];
                    out[(size_t)T * TOPK + (size_t)token * TOPK + k] = wsel[k] * inv;
                }
            }
        }
        __syncthreads();
    }
}

// ---------------------------------------------------------------------------
extern "C" void kernel_launch(void* const* d_in, const int* in_sizes, int n_in,
                              void* d_out, int out_size)
{
    const float* X    = (const float*)d_in[0];
    const float* W    = (const float*)d_in[1];
    const float* bias = (const float*)d_in[2];
    float* out = (float*)d_out;

    const int T = in_sizes[0] / HIDDEN;          // 16384

    cudaFuncSetAttribute(router_fused,
                         cudaFuncAttributeMaxDynamicSharedMemorySize, SMEM_BYTES);

    zero_ctr_kernel<<<1, 1>>>();
    router_fused<<<T / TM, 512, SMEM_BYTES>>>(X, W, bias, out, T);
    refine_kernel<<<256, 256>>>(X, W, bias, out, T);
}

// round 17
// speedup vs baseline: 1.7810x; 1.7810x over previous
#include <cuda_runtime.h>
#include <math.h>
#include <stdint.h>

#define HIDDEN 4096
#define NEXP   128
#define TOPK   8
#define TM     128
#define TK     16
#define NCHUNK (HIDDEN / TK)          // 256

#define XS_ROW 256                    // floats per k-row of duplicated A
#define WS_ROW 192                    // floats per k-row of B (16 blocks * 12)
#define XS_B   (TK * XS_ROW * 4)      // 16384 B
#define WS_B   (TK * WS_ROW * 4)      // 12288 B
#define STAGE_B (XS_B + WS_B)         // 28672 B
#define LPITCH 132
#define SMEM_BYTES (TM * LPITCH * 4)  // 67584 >= 2*STAGE_B (57344)

// packed fp32 FMA: d.lo += a.lo*b.lo ; d.hi += a.hi*b.hi  (IEEE fp32 lanes)
__device__ __forceinline__ void ffma2(unsigned long long& d,
                                      unsigned long long a,
                                      unsigned long long b) {
    asm("fma.rn.f32x2 %0, %1, %2, %0;" : "+l"(d) : "l"(a), "l"(b));
}

// ---------------------------------------------------------------------------
// Fused router: packed-fp32 (f32x2) SGEMM  logits = X @ W^T  -> smem logits
// -> sigmoid -> top-8 (score = sigmoid + bias, lowest-index tie-break)
// -> normalize -> out = [indices_as_float | weights].
// One CTA per 128 tokens, 256 threads. Thread (tx=tid&15, ty=tid>>4) owns an
// 8(token) x 8(expert) micro-tile held as 8x4 packed expert-pairs.
// TK=16 per stage (256 barriers total). Numerics are bit-identical to the
// round-1 scalar fp32 kernel (sequential-k accumulation per output).
// ---------------------------------------------------------------------------
__global__ void __launch_bounds__(256, 1) router_fused(
    const float* __restrict__ X, const float* __restrict__ W,
    const float* __restrict__ bias, float* __restrict__ out, int T)
{
    extern __shared__ char smem[];
    const int tid  = threadIdx.x;
    const int wid  = tid >> 5;
    const int lane = tid & 31;
    const int tx   = tid & 15;         // expert block (8 experts)
    const int ty   = tid >> 4;         // token block  (8 tokens)
    const int m0   = blockIdx.x * TM;

    const int lr   = tid >> 1;         // load row 0..127
    const int lc   = (tid & 1) * 8;    // k offset 0 or 8

    unsigned long long acc[8][4];
#pragma unroll
    for (int i = 0; i < 8; i++)
#pragma unroll
        for (int j = 0; j < 4; j++) acc[i][j] = 0ull;

    const float* xptr = X + (size_t)(m0 + lr) * HIDDEN + lc;
    const float* wptr = W + (size_t)lr * HIDDEN + lc;

    // W smem slot for this loader thread (block pitch 12 floats = 48 B)
    const int wslot = ((lr >> 3) * 12 + (lr & 7)) * 4;

    float4 xa0, xa1, wa0, wa1;

    // ---- prologue: chunk 0 -> stage 0 ----
    xa0 = *(const float4*)(xptr);
    xa1 = *(const float4*)(xptr + 4);
    wa0 = *(const float4*)(wptr);
    wa1 = *(const float4*)(wptr + 4);
    {
        char* sp = smem;
        const float xv[8] = {xa0.x, xa0.y, xa0.z, xa0.w, xa1.x, xa1.y, xa1.z, xa1.w};
        const float wv[8] = {wa0.x, wa0.y, wa0.z, wa0.w, wa1.x, wa1.y, wa1.z, wa1.w};
#pragma unroll
        for (int j = 0; j < 8; j++) {
            *(float2*)(sp + (lc + j) * (XS_ROW * 4) + lr * 8) = make_float2(xv[j], xv[j]);
            *(float*)(sp + XS_B + (lc + j) * (WS_ROW * 4) + wslot) = wv[j];
        }
    }

    // ---- main loop: compute chunk c from stage c&1, prefetch+store c+1 ----
    for (int c = 0; c < NCHUNK; c++) {
        __syncthreads();
        const char* sp = smem + (c & 1) * STAGE_B;

        if (c + 1 < NCHUNK) {
            xa0 = *(const float4*)(xptr + (c + 1) * TK);
            xa1 = *(const float4*)(xptr + (c + 1) * TK + 4);
            wa0 = *(const float4*)(wptr + (c + 1) * TK);
            wa1 = *(const float4*)(wptr + (c + 1) * TK + 4);
        }

#pragma unroll
        for (int kk = 0; kk < TK; kk++) {
            const char* xrow = sp + kk * (XS_ROW * 4) + ty * 64;
            const char* wrow = sp + XS_B + kk * (WS_ROW * 4) + tx * 48;

            ulonglong2 a01 = *(const ulonglong2*)(xrow);
            ulonglong2 a23 = *(const ulonglong2*)(xrow + 16);
            ulonglong2 a45 = *(const ulonglong2*)(xrow + 32);
            ulonglong2 a67 = *(const ulonglong2*)(xrow + 48);
            ulonglong2 b01 = *(const ulonglong2*)(wrow);
            ulonglong2 b23 = *(const ulonglong2*)(wrow + 16);

            unsigned long long ar[8] = {a01.x, a01.y, a23.x, a23.y,
                                        a45.x, a45.y, a67.x, a67.y};
            unsigned long long br[4] = {b01.x, b01.y, b23.x, b23.y};
#pragma unroll
            for (int i = 0; i < 8; i++)
#pragma unroll
                for (int j = 0; j < 4; j++)
                    ffma2(acc[i][j], ar[i], br[j]);
        }

        if (c + 1 < NCHUNK) {
            char* sn = smem + ((c + 1) & 1) * STAGE_B;
            const float xv[8] = {xa0.x, xa0.y, xa0.z, xa0.w, xa1.x, xa1.y, xa1.z, xa1.w};
            const float wv[8] = {wa0.x, wa0.y, wa0.z, wa0.w, wa1.x, wa1.y, wa1.z, wa1.w};
#pragma unroll
            for (int j = 0; j < 8; j++) {
                *(float2*)(sn + (lc + j) * (XS_ROW * 4) + lr * 8) = make_float2(xv[j], xv[j]);
                *(float*)(sn + XS_B + (lc + j) * (WS_ROW * 4) + wslot) = wv[j];
            }
        }
    }

    // ---- epilogue: unpack accumulators -> smem logits ----
    __syncthreads();
    float* L = (float*)smem;   // [128][LPITCH]
#pragma unroll
    for (int i = 0; i < 8; i++) {
        const int r = ty * 8 + i;
#pragma unroll
        for (int j = 0; j < 4; j++) {
            float2 v = *(float2*)&acc[i][j];         // (expert e, e+1)
            *(float2*)&L[r * LPITCH + tx * 8 + j * 2] = v;
        }
    }
    __syncthreads();

    // ---- fused top-k: warp w handles rows w*16 .. w*16+15 ----
    float bv[4];
#pragma unroll
    for (int q = 0; q < 4; q++) bv[q] = bias[q * 32 + lane];

    for (int rr = 0; rr < 16; rr++) {
        const int row = wid * 16 + rr;
        const float* Lr = L + row * LPITCH;

        float sv[4], wv[4];
#pragma unroll
        for (int q = 0; q < 4; q++) {
            float sc = 1.f / (1.f + expf(-Lr[q * 32 + lane]));
            wv[q] = sc;
            sv[q] = sc + bv[q];
        }

        float wsel[TOPK];
        int   isel[TOPK];
        float wsum = 0.f;
#pragma unroll
        for (int k = 0; k < TOPK; k++) {
            float bs = -INFINITY; int bi = 0x7fffffff; float bw = 0.f;
#pragma unroll
            for (int q = 0; q < 4; q++) {
                int e = q * 32 + lane;
                if (sv[q] > bs || (sv[q] == bs && e < bi)) { bs = sv[q]; bi = e; bw = wv[q]; }
            }
#pragma unroll
            for (int off = 16; off; off >>= 1) {
                float os = __shfl_xor_sync(0xffffffffu, bs, off);
                int   oi = __shfl_xor_sync(0xffffffffu, bi, off);
                float ow = __shfl_xor_sync(0xffffffffu, bw, off);
                if (os > bs || (os == bs && oi < bi)) { bs = os; bi = oi; bw = ow; }
            }
            isel[k] = bi; wsel[k] = bw; wsum += bw;
#pragma unroll
            for (int q = 0; q < 4; q++)
                if (q * 32 + lane == bi) sv[q] = -INFINITY;
        }

        if (lane == 0) {
            const int token = m0 + row;
            float inv = 1.f / (wsum + 1e-20f);   // ROUTED_SCALING = 1.0
#pragma unroll
            for (int k = 0; k < TOPK; k++) {
                out[(size_t)token * TOPK + k]                    = (float)isel[k];
                out[(size_t)T * TOPK + (size_t)token * TOPK + k] = wsel[k] * inv;
            }
        }
    }
}

// ---------------------------------------------------------------------------
extern "C" void kernel_launch(void* const* d_in, const int* in_sizes, int n_in,
                              void* d_out, int out_size)
{
    const float* X    = (const float*)d_in[0];   // hidden_states [T, 4096]
    const float* W    = (const float*)d_in[1];   // weight [128, 4096]
    const float* bias = (const float*)d_in[2];   // e_score_correction_bias [128]
    float* out = (float*)d_out;

    const int T = in_sizes[0] / HIDDEN;          // 16384

    cudaFuncSetAttribute(router_fused,
                         cudaFuncAttributeMaxDynamicSharedMemorySize, SMEM_BYTES);
    router_fused<<<T / TM, 256, SMEM_BYTES>>>(X, W, bias, out, T);
}